// round 1
// baseline (speedup 1.0000x reference)
#include <cuda_runtime.h>
#include <math.h>

// ---------------------------------------------------------------------------
// Fused: out = gelu_tanh(x) * gate(row)
//   gate = exp(-tau * cos_sim) * (1 + w * relu(tanh(sigma * mean|z|) - surp_ema))
//   z = (x - mu) / (std + 1e-5),  std = sqrt(max(ema_sq - mu^2, 1e-4))
//   cos_sim = clip(<out, ema_n> / max(||out||, 1e-12), -1, 1)
// Shapes: x [B=4, T=4096, D=2048] fp32. rows = 16384.
// ---------------------------------------------------------------------------

#define D_MAX 4096

__device__ float g_mu[D_MAX];
__device__ float g_inv_std[D_MAX];   // 1/(std + 1e-5)
__device__ float g_ema_n[D_MAX];     // ema_out / max(||ema_out||, 1e-12)
__device__ float g_scal[4];          // tau, sigma, w, surp_ema

__device__ __forceinline__ float softplus_f(float v) {
    return (v > 20.0f) ? v : log1pf(expf(v));
}

__global__ void prep_kernel(const float* __restrict__ ema_mean,
                            const float* __restrict__ ema_sq,
                            const float* __restrict__ ema_out,
                            const float* __restrict__ surp_ema,
                            const float* __restrict__ log_tau,
                            const float* __restrict__ log_sigma,
                            const float* __restrict__ log_w,
                            int D) {
    __shared__ float red[256];
    int tid = threadIdx.x;
    float ss = 0.0f;
    for (int d = tid; d < D; d += 256) {
        float mu  = ema_mean[d];
        float var = fmaxf(ema_sq[d] - mu * mu, 1e-4f);
        g_mu[d]      = mu;
        g_inv_std[d] = 1.0f / (sqrtf(var) + 1e-5f);
        float e = ema_out[d];
        ss += e * e;
    }
    red[tid] = ss;
    __syncthreads();
    for (int s = 128; s > 0; s >>= 1) {
        if (tid < s) red[tid] += red[tid + s];
        __syncthreads();
    }
    float inv_norm = 1.0f / fmaxf(sqrtf(red[0]), 1e-12f);
    for (int d = tid; d < D; d += 256) {
        g_ema_n[d] = ema_out[d] * inv_norm;
    }
    if (tid == 0) {
        g_scal[0] = expf(log_tau[0]);         // tau
        g_scal[1] = softplus_f(log_sigma[0]); // sigma
        g_scal[2] = softplus_f(log_w[0]);     // w
        g_scal[3] = surp_ema[0];
    }
}

__device__ __forceinline__ float gelu_tanh(float x) {
    const float c = 0.7978845608028654f; // sqrt(2/pi)
    float x3 = x * x * x;
    float t = tanhf(c * (x + 0.044715f * x3));
    return 0.5f * x * (1.0f + t);
}

__device__ __forceinline__ float warp_sum(float v) {
    #pragma unroll
    for (int o = 16; o > 0; o >>= 1)
        v += __shfl_xor_sync(0xffffffffu, v, o);
    return v;
}

// One CTA per row. 256 threads, 8 elems/thread (2x float4). D must be a
// multiple of 1024.
__global__ __launch_bounds__(256)
void gelu_gate_kernel(const float* __restrict__ x,
                      float* __restrict__ out,
                      int D) {
    const long long row = blockIdx.x;
    const float4* __restrict__ xr = (const float4*)(x + row * (long long)D);
    float4* __restrict__ orow     = (float4*)(out + row * (long long)D);
    const float4* __restrict__ muv = (const float4*)g_mu;
    const float4* __restrict__ isv = (const float4*)g_inv_std;
    const float4* __restrict__ env = (const float4*)g_ema_n;

    const int tid  = threadIdx.x;
    const int nIt  = D >> 10;      // D / 1024 (256 threads * 4 floats)

    float vout[2][4];              // nIt <= 2 for D=2048
    float s_absz = 0.0f, s_sq = 0.0f, s_dot = 0.0f;

    #pragma unroll 2
    for (int i = 0; i < nIt; i++) {
        int idx4 = i * 256 + tid;
        float4 xv = xr[idx4];
        float4 mu = muv[idx4];
        float4 is = isv[idx4];
        float4 en = env[idx4];

        float xs[4] = {xv.x, xv.y, xv.z, xv.w};
        float ms[4] = {mu.x, mu.y, mu.z, mu.w};
        float ss[4] = {is.x, is.y, is.z, is.w};
        float es[4] = {en.x, en.y, en.z, en.w};

        #pragma unroll
        for (int j = 0; j < 4; j++) {
            float xj = xs[j];
            float o  = gelu_tanh(xj);
            vout[i][j] = o;
            s_absz += fabsf((xj - ms[j]) * ss[j]);
            s_sq   += o * o;
            s_dot  += o * es[j];
        }
    }

    // Block reduction of the 3 sums (8 warps).
    __shared__ float red[3][8];
    __shared__ float s_gate;
    int wid = tid >> 5;
    int lid = tid & 31;

    s_absz = warp_sum(s_absz);
    s_sq   = warp_sum(s_sq);
    s_dot  = warp_sum(s_dot);
    if (lid == 0) {
        red[0][wid] = s_absz;
        red[1][wid] = s_sq;
        red[2][wid] = s_dot;
    }
    __syncthreads();
    if (tid == 0) {
        float a = 0.0f, b = 0.0f, c = 0.0f;
        #pragma unroll
        for (int k = 0; k < 8; k++) { a += red[0][k]; b += red[1][k]; c += red[2][k]; }
        float tau   = g_scal[0];
        float sigma = g_scal[1];
        float w     = g_scal[2];
        float surp  = g_scal[3];

        float mean_absz = a / (float)D;
        float surp_raw  = tanhf(sigma * mean_absz);
        float surp_mod  = fmaxf(surp_raw - surp, 0.0f);

        float nrm = sqrtf(b);
        float cs  = c / fmaxf(nrm, 1e-12f);
        cs = fminf(fmaxf(cs, -1.0f), 1.0f);

        s_gate = expf(-tau * cs) * (1.0f + w * surp_mod);
    }
    __syncthreads();
    float gate = s_gate;

    #pragma unroll 2
    for (int i = 0; i < nIt; i++) {
        int idx4 = i * 256 + tid;
        float4 ov;
        ov.x = vout[i][0] * gate;
        ov.y = vout[i][1] * gate;
        ov.z = vout[i][2] * gate;
        ov.w = vout[i][3] * gate;
        orow[idx4] = ov;
    }
}

extern "C" void kernel_launch(void* const* d_in, const int* in_sizes, int n_in,
                              void* d_out, int out_size) {
    const float* x        = (const float*)d_in[0];
    const float* ema_mean = (const float*)d_in[1];
    const float* ema_sq   = (const float*)d_in[2];
    const float* ema_out  = (const float*)d_in[3];
    const float* surp_ema = (const float*)d_in[4];
    const float* log_tau  = (const float*)d_in[5];
    const float* log_sig  = (const float*)d_in[6];
    const float* log_w    = (const float*)d_in[7];
    float* out = (float*)d_out;

    int D = in_sizes[1];             // 2048
    long long total = (long long)in_sizes[0];
    int rows = (int)(total / D);     // 16384

    prep_kernel<<<1, 256>>>(ema_mean, ema_sq, ema_out, surp_ema,
                            log_tau, log_sig, log_w, D);
    gelu_gate_kernel<<<rows, 256>>>(x, out, D);
}

// round 2
// speedup vs baseline: 1.1455x; 1.1455x over previous
#include <cuda_runtime.h>
#include <math.h>

// ---------------------------------------------------------------------------
// Fully fused single kernel:
//   out = gelu_tanh(x) * gate(row)
//   gate = exp(-tau*cos_sim) * (1 + w*relu(tanh(sigma*mean|z|) - surp_ema))
// Shapes fixed by dataset: x [4,4096,2048] fp32 -> rows=16384, D=2048.
// Each CTA: 256 threads, 8 columns/thread (2x float4), 8 rows per CTA.
// Channel stats (mu, inv_std, ema_n) live in registers, amortized over rows.
// ---------------------------------------------------------------------------

#define R_PER_CTA 8

__device__ __forceinline__ float ex2f(float v) {
    float y; asm("ex2.approx.f32 %0, %1;" : "=f"(y) : "f"(v)); return y;
}
__device__ __forceinline__ float rcpf(float v) {
    float y; asm("rcp.approx.f32 %0, %1;" : "=f"(y) : "f"(v)); return y;
}

// gelu_tanh(x) = 0.5x(1+tanh(c(x+0.044715x^3))) = x * sigmoid(2c(x+0.044715x^3))
//             = x * rcp(1 + ex2(x*(A + B*x^2)))
// A = -2*log2(e)*c,  B = A*0.044715,  c = sqrt(2/pi)
__device__ __forceinline__ float gelu_fast(float x) {
    const float A = -2.30220822f;
    const float B = -0.10294324f;
    float arg = x * fmaf(x * x, B, A);
    return x * rcpf(1.0f + ex2f(arg));
}

// tanh(y) = 2/(1+exp(-2y)) - 1
__device__ __forceinline__ float tanh_fast(float y) {
    return fmaf(2.0f, rcpf(1.0f + ex2f(-2.88539008f * y)), -1.0f);
}

__device__ __forceinline__ float softplus_f(float v) {
    return (v > 20.0f) ? v : log1pf(expf(v));
}

__device__ __forceinline__ float warp_sum(float v) {
    #pragma unroll
    for (int o = 16; o > 0; o >>= 1)
        v += __shfl_xor_sync(0xffffffffu, v, o);
    return v;
}

__global__ __launch_bounds__(256)
void fused_gelu_gate(const float* __restrict__ x,
                     const float* __restrict__ ema_mean,
                     const float* __restrict__ ema_sq,
                     const float* __restrict__ ema_out,
                     const float* __restrict__ surp_ema,
                     const float* __restrict__ log_tau,
                     const float* __restrict__ log_sigma,
                     const float* __restrict__ log_w,
                     float* __restrict__ out,
                     int rows) {
    const int D = 2048;
    const int tid = threadIdx.x;
    const int wid = tid >> 5;
    const int lid = tid & 31;
    const int i0 = tid;          // float4 index 0..511
    const int i1 = tid + 256;

    __shared__ float red[2][3][8];

    // ---- per-thread channel stats (registers, reused across all rows) ----
    const float4* M4 = (const float4*)ema_mean;
    const float4* Q4 = (const float4*)ema_sq;
    const float4* E4 = (const float4*)ema_out;

    float4 m0 = M4[i0], m1 = M4[i1];
    float4 q0 = Q4[i0], q1 = Q4[i1];
    float4 e0 = E4[i0], e1 = E4[i1];

    float mu[8]  = {m0.x, m0.y, m0.z, m0.w, m1.x, m1.y, m1.z, m1.w};
    float qq[8]  = {q0.x, q0.y, q0.z, q0.w, q1.x, q1.y, q1.z, q1.w};
    float en[8]  = {e0.x, e0.y, e0.z, e0.w, e1.x, e1.y, e1.z, e1.w};
    float is[8];
    float ess = 0.0f;
    #pragma unroll
    for (int j = 0; j < 8; j++) {
        float var = fmaxf(qq[j] - mu[j] * mu[j], 1e-4f);
        is[j] = rcpf(sqrtf(var) + 1e-5f);
        ess += en[j] * en[j];
    }

    // block reduce ema_out norm (block covers entire D)
    ess = warp_sum(ess);
    if (lid == 0) red[0][0][wid] = ess;
    __syncthreads();
    float tot = 0.0f;
    #pragma unroll
    for (int k = 0; k < 8; k++) tot += red[0][0][k];
    float inv_norm = rcpf(fmaxf(sqrtf(tot), 1e-12f));
    #pragma unroll
    for (int j = 0; j < 8; j++) en[j] *= inv_norm;
    __syncthreads();   // red[] reused below

    // ---- scalars (redundant per thread; broadcast loads) ----
    float tau   = expf(log_tau[0]);
    float sigma = softplus_f(log_sigma[0]);
    float w     = softplus_f(log_w[0]);
    float surp  = surp_ema[0];

    // ---- row loop ----
    long long row0 = (long long)blockIdx.x * R_PER_CTA;
    const float* xbase = x + row0 * D;
    float*       obase = out + row0 * D;

    const float4* xr0 = (const float4*)xbase;
    float4 xa = __ldcs(xr0 + i0);
    float4 xb = __ldcs(xr0 + i1);

    int par = 0;
    #pragma unroll 1
    for (int r = 0; r < R_PER_CTA; r++) {
        // prefetch next row (clamped; last iter re-reads same row, L2 hit)
        int rn = (r + 1 < R_PER_CTA) ? r + 1 : r;
        const float4* xrn = (const float4*)(xbase + (long long)rn * D);
        float4 na = __ldcs(xrn + i0);
        float4 nb = __ldcs(xrn + i1);

        float xs[8] = {xa.x, xa.y, xa.z, xa.w, xb.x, xb.y, xb.z, xb.w};
        float vo[8];
        float s_absz = 0.0f, s_sq = 0.0f, s_dot = 0.0f;
        #pragma unroll
        for (int j = 0; j < 8; j++) {
            float xj = xs[j];
            float o  = gelu_fast(xj);
            vo[j] = o;
            s_absz += fabsf((xj - mu[j]) * is[j]);
            s_sq   = fmaf(o, o, s_sq);
            s_dot  = fmaf(o, en[j], s_dot);
        }

        s_absz = warp_sum(s_absz);
        s_sq   = warp_sum(s_sq);
        s_dot  = warp_sum(s_dot);
        if (lid == 0) {
            red[par][0][wid] = s_absz;
            red[par][1][wid] = s_sq;
            red[par][2][wid] = s_dot;
        }
        __syncthreads();
        float a = 0.0f, b = 0.0f, c = 0.0f;
        #pragma unroll
        for (int k = 0; k < 8; k++) {
            a += red[par][0][k];
            b += red[par][1][k];
            c += red[par][2][k];
        }

        // gate (computed redundantly by every thread; all-fast ops)
        float mean_absz = a * (1.0f / 2048.0f);
        float surp_mod  = fmaxf(tanh_fast(sigma * mean_absz) - surp, 0.0f);
        float cs = c * rsqrtf(fmaxf(b, 1e-24f));
        cs = fminf(fmaxf(cs, -1.0f), 1.0f);
        float gate = ex2f(-tau * cs * 1.44269504f) * fmaf(w, surp_mod, 1.0f);

        float4* orow = (float4*)(obase + (long long)r * D);
        float4 o0 = {vo[0] * gate, vo[1] * gate, vo[2] * gate, vo[3] * gate};
        float4 o1 = {vo[4] * gate, vo[5] * gate, vo[6] * gate, vo[7] * gate};
        __stcs(orow + i0, o0);
        __stcs(orow + i1, o1);

        xa = na; xb = nb;
        par ^= 1;
    }
}

extern "C" void kernel_launch(void* const* d_in, const int* in_sizes, int n_in,
                              void* d_out, int out_size) {
    const float* x        = (const float*)d_in[0];
    const float* ema_mean = (const float*)d_in[1];
    const float* ema_sq   = (const float*)d_in[2];
    const float* ema_out  = (const float*)d_in[3];
    const float* surp_ema = (const float*)d_in[4];
    const float* log_tau  = (const float*)d_in[5];
    const float* log_sig  = (const float*)d_in[6];
    const float* log_w    = (const float*)d_in[7];
    float* out = (float*)d_out;

    int D = in_sizes[1];                       // 2048
    long long total = (long long)in_sizes[0];  // 33554432
    int rows = (int)(total / D);               // 16384
    int grid = rows / R_PER_CTA;               // 2048

    fused_gelu_gate<<<grid, 256>>>(x, ema_mean, ema_sq, ema_out, surp_ema,
                                   log_tau, log_sig, log_w, out, rows);
}

// round 3
// speedup vs baseline: 1.2249x; 1.0693x over previous
#include <cuda_runtime.h>
#include <math.h>

// ---------------------------------------------------------------------------
// out = gelu_tanh(x) * gate(row)
// gate = exp(-tau*cos) * (1 + w*relu(tanh(sigma*mean|z|) - surp_ema))
// x [4,4096,2048] fp32 -> 16384 rows, D=2048.
// CTA: 256 threads, 8 cols/thread (2x float4), 8 rows/CTA, depth-2 row prefetch.
// ---------------------------------------------------------------------------

#define R_PER_CTA 8

__device__ __forceinline__ float ex2f(float v) {
    float y; asm("ex2.approx.f32 %0, %1;" : "=f"(y) : "f"(v)); return y;
}
__device__ __forceinline__ float rcpf(float v) {
    float y; asm("rcp.approx.f32 %0, %1;" : "=f"(y) : "f"(v)); return y;
}
__device__ __forceinline__ float tanhf_hw(float v) {
    float y; asm("tanh.approx.f32 %0, %1;" : "=f"(y) : "f"(v)); return y;
}

__device__ __forceinline__ float softplus_f(float v) {
    return (v > 20.0f) ? v : log1pf(expf(v));
}

__device__ __forceinline__ float warp_sum(float v) {
    #pragma unroll
    for (int o = 16; o > 0; o >>= 1)
        v += __shfl_xor_sync(0xffffffffu, v, o);
    return v;
}

// gelu = 0.5x + 0.5x * tanh(x*(C1 + C2*x^2))
__device__ __forceinline__ float gelu_hw(float x) {
    const float C1 = 0.7978845608f;   // sqrt(2/pi)
    const float C2 = 0.0356774081f;   // C1 * 0.044715
    float u = x * fmaf(x * x, C2, C1);
    float t = tanhf_hw(u);
    float h = 0.5f * x;
    return fmaf(h, t, h);
}

__global__ __launch_bounds__(256, 3)
void fused_gelu_gate(const float* __restrict__ x,
                     const float* __restrict__ ema_mean,
                     const float* __restrict__ ema_sq,
                     const float* __restrict__ ema_out,
                     const float* __restrict__ surp_ema,
                     const float* __restrict__ log_tau,
                     const float* __restrict__ log_sigma,
                     const float* __restrict__ log_w,
                     float* __restrict__ out) {
    const int D = 2048;
    const int tid = threadIdx.x;
    const int wid = tid >> 5;
    const int lid = tid & 31;
    const int i0 = tid;
    const int i1 = tid + 256;

    __shared__ float4 red[8];
    __shared__ float s_bcast;

    // ---- channel stats in registers ----
    const float4* M4 = (const float4*)ema_mean;
    const float4* Q4 = (const float4*)ema_sq;
    const float4* E4 = (const float4*)ema_out;

    float4 m0 = M4[i0], m1 = M4[i1];
    float4 q0 = Q4[i0], q1 = Q4[i1];
    float4 e0 = E4[i0], e1 = E4[i1];

    float mu[8]   = {m0.x, m0.y, m0.z, m0.w, m1.x, m1.y, m1.z, m1.w};
    float qq[8]   = {q0.x, q0.y, q0.z, q0.w, q1.x, q1.y, q1.z, q1.w};
    float en[8]   = {e0.x, e0.y, e0.z, e0.w, e1.x, e1.y, e1.z, e1.w};
    float is[8], nmis[8];
    float ess = 0.0f;
    #pragma unroll
    for (int j = 0; j < 8; j++) {
        float var = fmaxf(qq[j] - mu[j] * mu[j], 1e-4f);
        is[j]   = rcpf(sqrtf(var) + 1e-5f);
        nmis[j] = -mu[j] * is[j];
        ess += en[j] * en[j];
    }

    // block reduce ||ema_out||^2 (block spans entire D)
    ess = warp_sum(ess);
    if (lid == 0) red[wid] = make_float4(ess, 0.0f, 0.0f, 0.0f);
    __syncthreads();
    if (wid == 0) {
        float v = red[lid & 7].x;
        #pragma unroll
        for (int o = 4; o > 0; o >>= 1) v += __shfl_xor_sync(0xffffffffu, v, o);
        if (tid == 0) s_bcast = rcpf(fmaxf(sqrtf(v), 1e-12f));
    }
    __syncthreads();
    {
        float inv_norm = s_bcast;
        #pragma unroll
        for (int j = 0; j < 8; j++) en[j] *= inv_norm;
    }

    // ---- scalars ----
    float tau   = expf(log_tau[0]);
    float sigma = softplus_f(log_sigma[0]);
    float w     = softplus_f(log_w[0]);
    float surp  = surp_ema[0];
    float ntau_l2e = -tau * 1.44269504f;

    // ---- row loop with depth-2 prefetch ----
    long long row0 = (long long)blockIdx.x * R_PER_CTA;
    const float* xbase = x + row0 * D;
    float*       obase = out + row0 * D;

    float4 ca  = __ldcs((const float4*)xbase + i0);
    float4 cb  = __ldcs((const float4*)xbase + i1);
    float4 n1a = __ldcs((const float4*)(xbase + D) + i0);
    float4 n1b = __ldcs((const float4*)(xbase + D) + i1);

    #pragma unroll 1
    for (int r = 0; r < R_PER_CTA; r++) {
        float4 n2a, n2b;
        if (r < R_PER_CTA - 2) {
            const float4* xrn = (const float4*)(xbase + (long long)(r + 2) * D);
            n2a = __ldcs(xrn + i0);
            n2b = __ldcs(xrn + i1);
        }

        float xs[8] = {ca.x, ca.y, ca.z, ca.w, cb.x, cb.y, cb.z, cb.w};
        float vo[8];
        float s_absz = 0.0f, s_sq = 0.0f, s_dot = 0.0f;
        #pragma unroll
        for (int j = 0; j < 8; j++) {
            float xj = xs[j];
            float o  = gelu_hw(xj);
            vo[j] = o;
            s_absz += fabsf(fmaf(xj, is[j], nmis[j]));
            s_sq   = fmaf(o, o, s_sq);
            s_dot  = fmaf(o, en[j], s_dot);
        }

        s_absz = warp_sum(s_absz);
        s_sq   = warp_sum(s_sq);
        s_dot  = warp_sum(s_dot);
        if (lid == 0) red[wid] = make_float4(s_absz, s_sq, s_dot, 0.0f);
        __syncthreads();

        if (wid == 0) {
            float4 v = red[lid & 7];
            #pragma unroll
            for (int o = 4; o > 0; o >>= 1) {
                v.x += __shfl_xor_sync(0xffffffffu, v.x, o);
                v.y += __shfl_xor_sync(0xffffffffu, v.y, o);
                v.z += __shfl_xor_sync(0xffffffffu, v.z, o);
            }
            if (lid == 0) {
                float mean_absz = v.x * (1.0f / 2048.0f);
                float surp_mod  = fmaxf(tanhf_hw(sigma * mean_absz) - surp, 0.0f);
                float cs = v.z * rsqrtf(fmaxf(v.y, 1e-24f));
                cs = fminf(fmaxf(cs, -1.0f), 1.0f);
                s_bcast = ex2f(ntau_l2e * cs) * fmaf(w, surp_mod, 1.0f);
            }
        }
        __syncthreads();
        float gate = s_bcast;

        float4* orow = (float4*)(obase + (long long)r * D);
        float4 o0 = {vo[0] * gate, vo[1] * gate, vo[2] * gate, vo[3] * gate};
        float4 o1 = {vo[4] * gate, vo[5] * gate, vo[6] * gate, vo[7] * gate};
        __stcs(orow + i0, o0);
        __stcs(orow + i1, o1);

        ca = n1a; cb = n1b;
        n1a = n2a; n1b = n2b;
    }
}

extern "C" void kernel_launch(void* const* d_in, const int* in_sizes, int n_in,
                              void* d_out, int out_size) {
    const float* x        = (const float*)d_in[0];
    const float* ema_mean = (const float*)d_in[1];
    const float* ema_sq   = (const float*)d_in[2];
    const float* ema_out  = (const float*)d_in[3];
    const float* surp_ema = (const float*)d_in[4];
    const float* log_tau  = (const float*)d_in[5];
    const float* log_sig  = (const float*)d_in[6];
    const float* log_w    = (const float*)d_in[7];
    float* out = (float*)d_out;

    int D = in_sizes[1];                       // 2048
    long long total = (long long)in_sizes[0];  // 33554432
    int rows = (int)(total / D);               // 16384
    int grid = rows / R_PER_CTA;               // 2048

    fused_gelu_gate<<<grid, 256>>>(x, ema_mean, ema_sq, ema_out, surp_ema,
                                   log_tau, log_sig, log_w, out);
}

// round 4
// speedup vs baseline: 1.3564x; 1.1074x over previous
#include <cuda_runtime.h>
#include <math.h>

// ---------------------------------------------------------------------------
// out = gelu_tanh(x) * gate(row)
// gate = exp(-tau*cos) * (1 + w*relu(tanh(sigma*mean|z|) - surp_ema))
// x [4,4096,2048] fp32 -> 16384 rows, D=2048.
// CTA: 256 threads, 8 cols/thread (2x float4), 8 rows/CTA, depth-1 prefetch.
// Channel stats live in SMEM (24KB/CTA) so regs fit 5 CTAs/SM (40 warps).
// ---------------------------------------------------------------------------

#define R_PER_CTA 8

__device__ __forceinline__ float ex2f(float v) {
    float y; asm("ex2.approx.f32 %0, %1;" : "=f"(y) : "f"(v)); return y;
}
__device__ __forceinline__ float rcpf(float v) {
    float y; asm("rcp.approx.f32 %0, %1;" : "=f"(y) : "f"(v)); return y;
}
__device__ __forceinline__ float tanhf_hw(float v) {
    float y; asm("tanh.approx.f32 %0, %1;" : "=f"(y) : "f"(v)); return y;
}
__device__ __forceinline__ float softplus_f(float v) {
    return (v > 20.0f) ? v : log1pf(expf(v));
}
__device__ __forceinline__ float warp_sum(float v) {
    #pragma unroll
    for (int o = 16; o > 0; o >>= 1)
        v += __shfl_xor_sync(0xffffffffu, v, o);
    return v;
}

// gelu = 0.5x + 0.5x * tanh(x*(C1 + C2*x^2))
__device__ __forceinline__ float gelu_hw(float x) {
    const float C1 = 0.7978845608f;   // sqrt(2/pi)
    const float C2 = 0.0356774081f;   // C1 * 0.044715
    float u = x * fmaf(x * x, C2, C1);
    float t = tanhf_hw(u);
    float h = 0.5f * x;
    return fmaf(h, t, h);
}

__global__ __launch_bounds__(256, 5)
void fused_gelu_gate(const float* __restrict__ x,
                     const float* __restrict__ ema_mean,
                     const float* __restrict__ ema_sq,
                     const float* __restrict__ ema_out,
                     const float* __restrict__ surp_ema,
                     const float* __restrict__ log_tau,
                     const float* __restrict__ log_sigma,
                     const float* __restrict__ log_w,
                     float* __restrict__ out) {
    const int D = 2048;
    const int tid = threadIdx.x;
    const int wid = tid >> 5;
    const int lid = tid & 31;
    const int i0 = tid;          // float4 index 0..255
    const int i1 = tid + 256;    // float4 index 256..511

    __shared__ float s_is[2048];
    __shared__ float s_nm[2048];
    __shared__ float s_en[2048];
    __shared__ float4 red[8];
    __shared__ float s_bcast;

    float4* IS4 = (float4*)s_is;
    float4* NM4 = (float4*)s_nm;
    float4* EN4 = (float4*)s_en;

    // ---- prologue: build channel stats in smem ----
    {
        const float4* M4 = (const float4*)ema_mean;
        const float4* Q4 = (const float4*)ema_sq;
        const float4* E4 = (const float4*)ema_out;
        float ess = 0.0f;
        #pragma unroll
        for (int c = 0; c < 2; c++) {
            int idx = (c == 0) ? i0 : i1;
            float4 m = M4[idx];
            float4 q = Q4[idx];
            float4 e = E4[idx];
            float4 isv, nmv;
            float mm[4] = {m.x, m.y, m.z, m.w};
            float qq[4] = {q.x, q.y, q.z, q.w};
            float* ip = &isv.x;
            float* np = &nmv.x;
            #pragma unroll
            for (int j = 0; j < 4; j++) {
                float var = fmaxf(qq[j] - mm[j] * mm[j], 1e-4f);
                float s = rcpf(sqrtf(var) + 1e-5f);
                ip[j] = s;
                np[j] = -mm[j] * s;
            }
            IS4[idx] = isv;
            NM4[idx] = nmv;
            EN4[idx] = e;
            ess = fmaf(e.x, e.x, ess);
            ess = fmaf(e.y, e.y, ess);
            ess = fmaf(e.z, e.z, ess);
            ess = fmaf(e.w, e.w, ess);
        }
        ess = warp_sum(ess);
        if (lid == 0) red[wid] = make_float4(ess, 0.f, 0.f, 0.f);
        __syncthreads();
        if (wid == 0) {
            float v = red[lid & 7].x;
            #pragma unroll
            for (int o = 4; o > 0; o >>= 1) v += __shfl_xor_sync(0xffffffffu, v, o);
            if (lid == 0) s_bcast = rcpf(fmaxf(sqrtf(v), 1e-12f));
        }
        __syncthreads();
        float inv_norm = s_bcast;
        float4 e0 = EN4[i0], e1 = EN4[i1];
        e0.x *= inv_norm; e0.y *= inv_norm; e0.z *= inv_norm; e0.w *= inv_norm;
        e1.x *= inv_norm; e1.y *= inv_norm; e1.z *= inv_norm; e1.w *= inv_norm;
        EN4[i0] = e0;
        EN4[i1] = e1;
        __syncthreads();
    }

    // ---- scalars ----
    float tau   = expf(log_tau[0]);
    float sigma = softplus_f(log_sigma[0]);
    float w     = softplus_f(log_w[0]);
    float surp  = surp_ema[0];
    float ntau_l2e = -tau * 1.44269504f;

    // ---- row loop, depth-1 prefetch ----
    long long row0 = (long long)blockIdx.x * R_PER_CTA;
    const float* xbase = x + row0 * D;
    float*       obase = out + row0 * D;

    float4 ca = __ldcs((const float4*)xbase + i0);
    float4 cb = __ldcs((const float4*)xbase + i1);

    #pragma unroll 1
    for (int r = 0; r < R_PER_CTA; r++) {
        float4 na, nb;
        if (r < R_PER_CTA - 1) {
            const float4* xrn = (const float4*)(xbase + (long long)(r + 1) * D);
            na = __ldcs(xrn + i0);
            nb = __ldcs(xrn + i1);
        }

        float vo[8];
        float s_absz = 0.0f, s_sq = 0.0f, s_dot = 0.0f;
        #pragma unroll
        for (int c = 0; c < 2; c++) {
            int idx = (c == 0) ? i0 : i1;
            float4 xv = (c == 0) ? ca : cb;
            float4 isv = IS4[idx];
            float4 nmv = NM4[idx];
            float4 env = EN4[idx];
            float xs[4] = {xv.x, xv.y, xv.z, xv.w};
            float ip[4] = {isv.x, isv.y, isv.z, isv.w};
            float np[4] = {nmv.x, nmv.y, nmv.z, nmv.w};
            float ep[4] = {env.x, env.y, env.z, env.w};
            #pragma unroll
            for (int j = 0; j < 4; j++) {
                float xj = xs[j];
                float o  = gelu_hw(xj);
                vo[c * 4 + j] = o;
                s_absz += fabsf(fmaf(xj, ip[j], np[j]));
                s_sq   = fmaf(o, o, s_sq);
                s_dot  = fmaf(o, ep[j], s_dot);
            }
        }

        s_absz = warp_sum(s_absz);
        s_sq   = warp_sum(s_sq);
        s_dot  = warp_sum(s_dot);
        if (lid == 0) red[wid] = make_float4(s_absz, s_sq, s_dot, 0.0f);
        __syncthreads();

        if (wid == 0) {
            float4 v = red[lid & 7];
            #pragma unroll
            for (int o = 4; o > 0; o >>= 1) {
                v.x += __shfl_xor_sync(0xffffffffu, v.x, o);
                v.y += __shfl_xor_sync(0xffffffffu, v.y, o);
                v.z += __shfl_xor_sync(0xffffffffu, v.z, o);
            }
            if (lid == 0) {
                float mean_absz = v.x * (1.0f / 2048.0f);
                float surp_mod  = fmaxf(tanhf_hw(sigma * mean_absz) - surp, 0.0f);
                float cs = v.z * rsqrtf(fmaxf(v.y, 1e-24f));
                cs = fminf(fmaxf(cs, -1.0f), 1.0f);
                s_bcast = ex2f(ntau_l2e * cs) * fmaf(w, surp_mod, 1.0f);
            }
        }
        __syncthreads();
        float gate = s_bcast;

        float4* orow = (float4*)(obase + (long long)r * D);
        float4 o0 = {vo[0] * gate, vo[1] * gate, vo[2] * gate, vo[3] * gate};
        float4 o1 = {vo[4] * gate, vo[5] * gate, vo[6] * gate, vo[7] * gate};
        __stcs(orow + i0, o0);
        __stcs(orow + i1, o1);

        ca = na; cb = nb;
    }
}

extern "C" void kernel_launch(void* const* d_in, const int* in_sizes, int n_in,
                              void* d_out, int out_size) {
    const float* x        = (const float*)d_in[0];
    const float* ema_mean = (const float*)d_in[1];
    const float* ema_sq   = (const float*)d_in[2];
    const float* ema_out  = (const float*)d_in[3];
    const float* surp_ema = (const float*)d_in[4];
    const float* log_tau  = (const float*)d_in[5];
    const float* log_sig  = (const float*)d_in[6];
    const float* log_w    = (const float*)d_in[7];
    float* out = (float*)d_out;

    int D = in_sizes[1];                       // 2048
    long long total = (long long)in_sizes[0];  // 33554432
    int rows = (int)(total / D);               // 16384
    int grid = rows / R_PER_CTA;               // 2048

    fused_gelu_gate<<<grid, 256>>>(x, ema_mean, ema_sq, ema_out, surp_ema,
                                   log_tau, log_sig, log_w, out);
}